// round 5
// baseline (speedup 1.0000x reference)
#include <cuda_runtime.h>
#include <cuda_bf16.h>
#include <cstdint>

// Problem constants (fixed by setup_inputs)
#define BMAX 16384
#define NROWS_MAX (BMAX * 5)

// ============================================================================
// Scratch (__device__ globals; no allocation allowed)
// ============================================================================
__device__ __nv_bfloat16 g_inp_hi[(size_t)NROWS_MAX * 160];  // 26 MB
__device__ __nv_bfloat16 g_inp_lo[(size_t)NROWS_MAX * 160];
__device__ __nv_bfloat16 g_h_hi[(size_t)NROWS_MAX * 512];    // 84 MB
__device__ __nv_bfloat16 g_h_lo[(size_t)NROWS_MAX * 512];
__device__ __nv_bfloat16 g_w1t_hi[512 * 160], g_w1t_lo[512 * 160];
__device__ __nv_bfloat16 g_w2t_hi[512 * 256], g_w2t_lo[512 * 256];

// ============================================================================
// Warp-MMA helpers (sm_80-era PTX: legal on compute_103, maps to HMMA)
// ============================================================================
#define LDSM_X4(r0, r1, r2, r3, addr) \
    asm volatile("ldmatrix.sync.aligned.m8n8.x4.shared.b16 {%0,%1,%2,%3}, [%4];" \
        : "=r"(r0), "=r"(r1), "=r"(r2), "=r"(r3) : "r"(addr))

__device__ __forceinline__ void mma16816(float* d, const uint32_t* a, const uint32_t* b) {
    asm volatile(
        "mma.sync.aligned.m16n8k16.row.col.f32.bf16.bf16.f32 "
        "{%0,%1,%2,%3}, {%4,%5,%6,%7}, {%8,%9}, {%0,%1,%2,%3};"
        : "+f"(d[0]), "+f"(d[1]), "+f"(d[2]), "+f"(d[3])
        : "r"(a[0]), "r"(a[1]), "r"(a[2]), "r"(a[3]), "r"(b[0]), "r"(b[1]));
}

__device__ __forceinline__ uint32_t smem_u32(const void* p) {
    uint32_t a;
    asm("{ .reg .u64 tmp; cvta.to.shared.u64 tmp, %1; cvt.u32.u64 %0, tmp; }"
        : "=r"(a) : "l"(p));
    return a;
}

__device__ __forceinline__ void split_bf16(float v, __nv_bfloat16& h, __nv_bfloat16& l) {
    h = __float2bfloat16_rn(v);
    l = __float2bfloat16_rn(v - __bfloat162float(h));
}

// ---------------------------------------------------------------------------
// K-edge (MMA) + fused prep: CTA = 16 batches = 320 edge-rows.
//   D[320 x 128] = relu(inp_mp @ mp_w + mp_b), aggregated over dst groups
//   -> g_inp cols 29..156 (bf16 hi/lo). Also fills cols 0..28 and zero pads.
// 640 threads = 20 warps: 10(M) x 2(N); warp tile m32 x n64; K=48 (3 ksteps).
// SMEM: bias 0..512; A_hi 512 (320x112B=35840); A_lo 36352; B_hi 72192
//   (128x112B=14336); B_lo 86528; end 100864. s_agg (16*5*128 f32 = 40960B)
//   aliases the A region (offset 512) after the MMA loop.
// ---------------------------------------------------------------------------
#define E_BIAS 0
#define E_AHI  512
#define E_ALO  36352
#define E_BHI  72192
#define E_BLO  86528
#define E_SMEM 100864
#define E_SAGG 512

__global__ __launch_bounds__(640, 1) void k_edge_mma(
    const float* __restrict__ obs, const float* __restrict__ act,
    const float* __restrict__ ag,  const float* __restrict__ g,
    const float* __restrict__ mp_w, const float* __restrict__ mp_b)
{
    extern __shared__ char smemc[];
    const uint32_t sbase = smem_u32(smemc);
    const int t    = threadIdx.x;
    const int wid  = t >> 5;
    const int lane = t & 31;
    const int b0   = blockIdx.x * 16;

    float* sb = reinterpret_cast<float*>(smemc + E_BIAS);
    if (t < 128) sb[t] = mp_b[t];

    // --- fused prep: g_inp cols 0..28 and zero cols 157..159 (16*5 rows) ---
    for (int idx = t; idx < 16 * 5 * 32; idx += 640) {
        int rl = idx >> 5;
        int c  = idx & 31;
        int b  = b0 + rl / 5;
        int n  = rl % 5;
        float v; int col;
        if (c < 4)       { v = act[b * 4 + c];                       col = c; }
        else if (c < 14) { v = obs[b * 85 + (c - 4)];                col = c; }
        else if (c < 29) { v = obs[b * 85 + 10 + n * 15 + (c - 14)]; col = c; }
        else             { v = 0.0f;                                  col = 128 + c; }
        __nv_bfloat16 h, l;
        split_bf16(v, h, l);
        size_t off = (size_t)(b0 * 5 + rl) * 160 + col;
        g_inp_hi[off] = h;
        g_inp_lo[off] = l;
    }

    // --- stage A: 320 rows x 46 cols gathered, bf16 hi/lo, stride 56 elems ---
    for (int idx = t; idx < 320 * 46; idx += 640) {
        int row = idx / 46;
        int k   = idx - row * 46;
        int b   = b0 + row / 20;
        int e   = row % 20;
        int src = e >> 2, rr = e & 3;
        int dst = (rr < src) ? rr : rr + 1;
        float v;
        if (k < 10)       v = obs[b * 85 + k];
        else if (k < 14)  v = act[b * 4 + (k - 10)];
        else if (k == 14) v = g[b * 30 + e]      - ag[b * 30 + e];
        else if (k == 15) v = g[b * 30 + e + 10] - ag[b * 30 + e + 10];
        else if (k < 31)  v = obs[b * 85 + 10 + src * 15 + (k - 16)];
        else              v = obs[b * 85 + 10 + dst * 15 + (k - 31)];
        __nv_bfloat16 h, l;
        split_bf16(v, h, l);
        *reinterpret_cast<__nv_bfloat16*>(smemc + E_AHI + row * 112 + k * 2) = h;
        *reinterpret_cast<__nv_bfloat16*>(smemc + E_ALO + row * 112 + k * 2) = l;
    }
    // zero A pad cols 46..55
    for (int idx = t; idx < 320 * 10; idx += 640) {
        int row = idx / 10;
        int k   = 46 + idx % 10;
        *reinterpret_cast<__nv_bfloat16*>(smemc + E_AHI + row * 112 + k * 2) = __nv_bfloat16(0.f);
        *reinterpret_cast<__nv_bfloat16*>(smemc + E_ALO + row * 112 + k * 2) = __nv_bfloat16(0.f);
    }
    // --- stage B: B[n][k] = mp_w[k*128+n], pad k 46..55 ---
    for (int idx = t; idx < 128 * 56; idx += 640) {
        int n = idx / 56;
        int k = idx - n * 56;
        float v = (k < 46) ? mp_w[k * 128 + n] : 0.0f;
        __nv_bfloat16 h, l;
        split_bf16(v, h, l);
        *reinterpret_cast<__nv_bfloat16*>(smemc + E_BHI + n * 112 + k * 2) = h;
        *reinterpret_cast<__nv_bfloat16*>(smemc + E_BLO + n * 112 + k * 2) = l;
    }
    __syncthreads();

    const int warp_m = wid % 10;   // 10 x 32 rows
    const int warp_n = wid / 10;   // 2 x 64 cols

    float acc[2][8][4];
#pragma unroll
    for (int mt = 0; mt < 2; mt++)
#pragma unroll
        for (int nt = 0; nt < 8; nt++)
#pragma unroll
            for (int j = 0; j < 4; j++) acc[mt][nt][j] = 0.0f;

    const int a_row  = warp_m * 32 + (lane & 15);
    const int a_ksub = (lane >> 4) * 8;
    const int b_row  = warp_n * 64 + (lane & 7) + ((lane >> 4) & 1) * 8;
    const int b_ksub = ((lane >> 3) & 1) * 8;

#pragma unroll
    for (int ks = 0; ks < 3; ks++) {
        const uint32_t a_off = (uint32_t)(a_row * 112 + (ks * 16 + a_ksub) * 2);
        const uint32_t b_off = (uint32_t)(b_row * 112 + (ks * 16 + b_ksub) * 2);
        uint32_t ahi[2][4], alo[2][4];
#pragma unroll
        for (int mt = 0; mt < 2; mt++) {
            LDSM_X4(ahi[mt][0], ahi[mt][1], ahi[mt][2], ahi[mt][3],
                    sbase + E_AHI + a_off + mt * 16 * 112);
            LDSM_X4(alo[mt][0], alo[mt][1], alo[mt][2], alo[mt][3],
                    sbase + E_ALO + a_off + mt * 16 * 112);
        }
#pragma unroll
        for (int p = 0; p < 4; p++) {
            uint32_t bh[4], bl[4];
            LDSM_X4(bh[0], bh[1], bh[2], bh[3],
                    sbase + E_BHI + b_off + p * 16 * 112);
            LDSM_X4(bl[0], bl[1], bl[2], bl[3],
                    sbase + E_BLO + b_off + p * 16 * 112);
#pragma unroll
            for (int mt = 0; mt < 2; mt++)
#pragma unroll
                for (int hh = 0; hh < 2; hh++) {
                    mma16816(acc[mt][p * 2 + hh], ahi[mt], &bh[hh * 2]);
                    mma16816(acc[mt][p * 2 + hh], ahi[mt], &bl[hh * 2]);
                    mma16816(acc[mt][p * 2 + hh], alo[mt], &bh[hh * 2]);
                }
        }
    }
    __syncthreads();   // all LDSM reads done before s_agg aliases the A region

    // --- epilogue: relu(+bias) -> smem atomic aggregation over (b,dst) ---
    float* s_agg = reinterpret_cast<float*>(smemc + E_SAGG);  // [16*5][128]
    for (int idx = t; idx < 16 * 5 * 128; idx += 640) s_agg[idx] = 0.0f;
    __syncthreads();

#pragma unroll
    for (int mt = 0; mt < 2; mt++)
#pragma unroll
        for (int nt = 0; nt < 8; nt++)
#pragma unroll
            for (int j = 0; j < 4; j++) {
                int row = warp_m * 32 + mt * 16 + (lane >> 2) + (j >> 1) * 8;
                int col = warp_n * 64 + nt * 8 + (lane & 3) * 2 + (j & 1);
                int bl  = row / 20;
                int e   = row % 20;
                int src = e >> 2, rr = e & 3;
                int dst = (rr < src) ? rr : rr + 1;
                float v = fmaxf(acc[mt][nt][j] + sb[col], 0.0f);
                atomicAdd(&s_agg[(bl * 5 + dst) * 128 + col], v);
            }
    __syncthreads();

    // --- write agg -> g_inp cols 29..156 (bf16 hi/lo) ---
    for (int idx = t; idx < 16 * 5 * 128; idx += 640) {
        int rl = idx >> 7;          // local row (b_local*5 + dst)
        int c  = idx & 127;
        __nv_bfloat16 h, l;
        split_bf16(s_agg[idx], h, l);
        size_t off = (size_t)(b0 * 5 + rl) * 160 + 29 + c;
        g_inp_hi[off] = h;
        g_inp_lo[off] = l;
    }
}

// ---------------------------------------------------------------------------
// K-wconv: transpose + bf16-split weights.
// ---------------------------------------------------------------------------
__global__ void k_wconv(const float* __restrict__ w1, const float* __restrict__ w3,
                        const float* __restrict__ w2, const float* __restrict__ w4)
{
    int idx = blockIdx.x * 256 + threadIdx.x;
    const int N1 = 512 * 160;
    const int N2 = 512 * 256;
    if (idx < N1) {
        int n = idx / 160, k = idx - n * 160;
        float v = 0.0f;
        if (k < 157) v = (n < 256) ? w1[k * 256 + n] : w3[k * 256 + (n - 256)];
        __nv_bfloat16 h, l;
        split_bf16(v, h, l);
        g_w1t_hi[idx] = h; g_w1t_lo[idx] = l;
    } else if (idx < N1 + N2) {
        int j = idx - N1;
        int n = j / 256, k = j - n * 256;
        float v = (n < 256) ? w2[k * 256 + n] : w4[k * 256 + (n - 256)];
        __nv_bfloat16 h, l;
        split_bf16(v, h, l);
        g_w2t_hi[j] = h; g_w2t_lo[j] = l;
    }
}

// ---------------------------------------------------------------------------
// K-init: out[b] = rho_b
// ---------------------------------------------------------------------------
__global__ void k_init(float* __restrict__ out,
                       const float* __restrict__ rb1, const float* __restrict__ rb2, int B)
{
    int i = blockIdx.x * 256 + threadIdx.x;
    if (i < B) { out[i] = rb1[0]; out[B + i] = rb2[0]; }
}

// ---------------------------------------------------------------------------
// K-phi1 (MMA): D[128m x 128n] = inp-tile @ w1t-block, K=160 (5 chunks of 32).
// ---------------------------------------------------------------------------
#define P1_BIAS 0
#define P1_AHI  512
#define P1_ALO  10752
#define P1_BHI  20992
#define P1_BLO  31232
#define P1_SMEM 41472

__global__ __launch_bounds__(256, 2) void k_phi1_mma(
    const float* __restrict__ phi_b1, const float* __restrict__ phi_b3)
{
    extern __shared__ char smemc[];
    const uint32_t sbase = smem_u32(smemc);
    const int t    = threadIdx.x;
    const int wid  = t >> 5;
    const int lane = t & 31;
    const int m0   = blockIdx.x * 128;
    const int nc   = blockIdx.y;            // which 128 of N=512

    float* sb = reinterpret_cast<float*>(smemc + P1_BIAS);
    if (t < 128) {
        int n = nc * 128 + t;
        sb[t] = (n < 256) ? phi_b1[n] : phi_b3[n - 256];
    }

    const int warp_m = wid & 3;
    const int warp_n = wid >> 2;

    float acc[2][8][4];
#pragma unroll
    for (int mt = 0; mt < 2; mt++)
#pragma unroll
        for (int nt = 0; nt < 8; nt++)
#pragma unroll
            for (int j = 0; j < 4; j++) acc[mt][nt][j] = 0.0f;

    const int a_row  = warp_m * 32 + (lane & 15);
    const int a_ksub = (lane >> 4) * 8;
    const int b_row  = warp_n * 64 + (lane & 7) + ((lane >> 4) & 1) * 8;
    const int b_ksub = ((lane >> 3) & 1) * 8;

    for (int kc = 0; kc < 5; kc++) {
        __syncthreads();
        for (int idx = t; idx < 128 * 4; idx += 256) {
            int row = idx >> 2, q = idx & 3;
            const uint4* sh = reinterpret_cast<const uint4*>(
                g_inp_hi + (size_t)(m0 + row) * 160 + kc * 32) + q;
            const uint4* sl = reinterpret_cast<const uint4*>(
                g_inp_lo + (size_t)(m0 + row) * 160 + kc * 32) + q;
            *reinterpret_cast<uint4*>(smemc + P1_AHI + row * 80 + q * 16) = *sh;
            *reinterpret_cast<uint4*>(smemc + P1_ALO + row * 80 + q * 16) = *sl;
        }
        for (int idx = t; idx < 128 * 4; idx += 256) {
            int n = idx >> 2, q = idx & 3;
            const uint4* sh = reinterpret_cast<const uint4*>(
                g_w1t_hi + (size_t)(nc * 128 + n) * 160 + kc * 32) + q;
            const uint4* sl = reinterpret_cast<const uint4*>(
                g_w1t_lo + (size_t)(nc * 128 + n) * 160 + kc * 32) + q;
            *reinterpret_cast<uint4*>(smemc + P1_BHI + n * 80 + q * 16) = *sh;
            *reinterpret_cast<uint4*>(smemc + P1_BLO + n * 80 + q * 16) = *sl;
        }
        __syncthreads();

#pragma unroll
        for (int ks = 0; ks < 2; ks++) {
            const uint32_t a_off = (uint32_t)(a_row * 80 + (ks * 16 + a_ksub) * 2);
            const uint32_t b_off = (uint32_t)(b_row * 80 + (ks * 16 + b_ksub) * 2);
            uint32_t ahi[2][4], alo[2][4];
#pragma unroll
            for (int mt = 0; mt < 2; mt++) {
                LDSM_X4(ahi[mt][0], ahi[mt][1], ahi[mt][2], ahi[mt][3],
                        sbase + P1_AHI + a_off + mt * 16 * 80);
                LDSM_X4(alo[mt][0], alo[mt][1], alo[mt][2], alo[mt][3],
                        sbase + P1_ALO + a_off + mt * 16 * 80);
            }
#pragma unroll
            for (int p = 0; p < 4; p++) {
                uint32_t bh[4], bl[4];
                LDSM_X4(bh[0], bh[1], bh[2], bh[3],
                        sbase + P1_BHI + b_off + p * 16 * 80);
                LDSM_X4(bl[0], bl[1], bl[2], bl[3],
                        sbase + P1_BLO + b_off + p * 16 * 80);
#pragma unroll
                for (int mt = 0; mt < 2; mt++)
#pragma unroll
                    for (int hh = 0; hh < 2; hh++) {
                        mma16816(acc[mt][p * 2 + hh], ahi[mt], &bh[hh * 2]);
                        mma16816(acc[mt][p * 2 + hh], ahi[mt], &bl[hh * 2]);
                        mma16816(acc[mt][p * 2 + hh], alo[mt], &bh[hh * 2]);
                    }
            }
        }
    }

#pragma unroll
    for (int mt = 0; mt < 2; mt++)
#pragma unroll
        for (int nt = 0; nt < 8; nt++) {
            int c = warp_n * 64 + nt * 8 + (lane & 3) * 2;
            float b0 = sb[c], b1 = sb[c + 1];
#pragma unroll
            for (int half = 0; half < 2; half++) {
                int row = warp_m * 32 + mt * 16 + (lane >> 2) + half * 8;
                float v0 = fmaxf(acc[mt][nt][half * 2]     + b0, 0.0f);
                float v1 = fmaxf(acc[mt][nt][half * 2 + 1] + b1, 0.0f);
                __nv_bfloat16 h0, l0, h1, l1;
                split_bf16(v0, h0, l0);
                split_bf16(v1, h1, l1);
                uint32_t ph = ((uint32_t)__bfloat16_as_ushort(h1) << 16) | __bfloat16_as_ushort(h0);
                uint32_t pl = ((uint32_t)__bfloat16_as_ushort(l1) << 16) | __bfloat16_as_ushort(l0);
                size_t off = (size_t)(m0 + row) * 512 + nc * 128 + c;
                *reinterpret_cast<uint32_t*>(g_h_hi + off) = ph;
                *reinterpret_cast<uint32_t*>(g_h_lo + off) = pl;
            }
        }
}

// ---------------------------------------------------------------------------
// K-phi2 (MMA): D[128m x 128n] = h-tile @ w2t-block, K=256 (4 chunks of 64).
// ---------------------------------------------------------------------------
#define SB_BIAS 0
#define SB_RHO  512
#define SB_SARR 1024
#define SB_AHI  1536
#define SB_ALO  19968
#define SB_BHI  38400
#define SB_BLO  56832
#define P2_SMEM 75264

__global__ __launch_bounds__(256, 2) void k_phi2_mma(
    const float* __restrict__ phi_b2, const float* __restrict__ phi_b4,
    const float* __restrict__ rho_w1, const float* __restrict__ rho_w2,
    float* __restrict__ out, int B)
{
    extern __shared__ char smemc[];
    const uint32_t sbase = smem_u32(smemc);
    const int t    = threadIdx.x;
    const int wid  = t >> 5;
    const int lane = t & 31;
    const int m0   = blockIdx.x * 128;
    const int br   = blockIdx.y;
    const int nc   = blockIdx.z;

    const float* bias = br ? phi_b4 : phi_b2;
    const float* rho  = br ? rho_w2 : rho_w1;

    float* sb    = reinterpret_cast<float*>(smemc + SB_BIAS);
    float* sr    = reinterpret_cast<float*>(smemc + SB_RHO);
    float* s_arr = reinterpret_cast<float*>(smemc + SB_SARR);

    if (t < 128) {
        sb[t] = bias[nc * 128 + t];
        sr[t] = rho[nc * 128 + t];
        s_arr[t] = 0.0f;
    }

    const int warp_m = wid & 3;
    const int warp_n = wid >> 2;

    float acc[2][8][4];
#pragma unroll
    for (int mt = 0; mt < 2; mt++)
#pragma unroll
        for (int nt = 0; nt < 8; nt++)
#pragma unroll
            for (int j = 0; j < 4; j++) acc[mt][nt][j] = 0.0f;

    const int a_row  = warp_m * 32 + (lane & 15);
    const int a_ksub = (lane >> 4) * 8;
    const int b_row  = warp_n * 64 + (lane & 7) + ((lane >> 4) & 1) * 8;
    const int b_ksub = ((lane >> 3) & 1) * 8;

    for (int kc = 0; kc < 4; kc++) {
        __syncthreads();
        for (int idx = t; idx < 128 * 8; idx += 256) {
            int row = idx >> 3, q = idx & 7;
            const uint4* sh = reinterpret_cast<const uint4*>(
                g_h_hi + (size_t)(m0 + row) * 512 + br * 256 + kc * 64) + q;
            const uint4* sl = reinterpret_cast<const uint4*>(
                g_h_lo + (size_t)(m0 + row) * 512 + br * 256 + kc * 64) + q;
            *reinterpret_cast<uint4*>(smemc + SB_AHI + row * 144 + q * 16) = *sh;
            *reinterpret_cast<uint4*>(smemc + SB_ALO + row * 144 + q * 16) = *sl;
        }
        for (int idx = t; idx < 128 * 8; idx += 256) {
            int n = idx >> 3, q = idx & 7;
            const uint4* sh = reinterpret_cast<const uint4*>(
                g_w2t_hi + (size_t)(br * 256 + nc * 128 + n) * 256 + kc * 64) + q;
            const uint4* sl = reinterpret_cast<const uint4*>(
                g_w2t_lo + (size_t)(br * 256 + nc * 128 + n) * 256 + kc * 64) + q;
            *reinterpret_cast<uint4*>(smemc + SB_BHI + n * 144 + q * 16) = *sh;
            *reinterpret_cast<uint4*>(smemc + SB_BLO + n * 144 + q * 16) = *sl;
        }
        __syncthreads();

#pragma unroll
        for (int ks = 0; ks < 4; ks++) {
            const uint32_t a_off = (uint32_t)(a_row * 144 + (ks * 16 + a_ksub) * 2);
            const uint32_t b_off = (uint32_t)(b_row * 144 + (ks * 16 + b_ksub) * 2);
            uint32_t ahi[2][4], alo[2][4];
#pragma unroll
            for (int mt = 0; mt < 2; mt++) {
                LDSM_X4(ahi[mt][0], ahi[mt][1], ahi[mt][2], ahi[mt][3],
                        sbase + SB_AHI + a_off + mt * 16 * 144);
                LDSM_X4(alo[mt][0], alo[mt][1], alo[mt][2], alo[mt][3],
                        sbase + SB_ALO + a_off + mt * 16 * 144);
            }
#pragma unroll
            for (int p = 0; p < 4; p++) {
                uint32_t bh[4], bl[4];
                LDSM_X4(bh[0], bh[1], bh[2], bh[3],
                        sbase + SB_BHI + b_off + p * 16 * 144);
                LDSM_X4(bl[0], bl[1], bl[2], bl[3],
                        sbase + SB_BLO + b_off + p * 16 * 144);
#pragma unroll
                for (int mt = 0; mt < 2; mt++)
#pragma unroll
                    for (int hh = 0; hh < 2; hh++) {
                        mma16816(acc[mt][p * 2 + hh], ahi[mt], &bh[hh * 2]);
                        mma16816(acc[mt][p * 2 + hh], ahi[mt], &bl[hh * 2]);
                        mma16816(acc[mt][p * 2 + hh], alo[mt], &bh[hh * 2]);
                    }
            }
        }
    }

#pragma unroll
    for (int mt = 0; mt < 2; mt++) {
        float s0 = 0.0f, s1 = 0.0f;
#pragma unroll
        for (int nt = 0; nt < 8; nt++) {
            int c = warp_n * 64 + nt * 8 + (lane & 3) * 2;
            float b0v = sb[c], b1v = sb[c + 1];
            float r0v = sr[c], r1v = sr[c + 1];
            s0 += fmaxf(acc[mt][nt][0] + b0v, 0.0f) * r0v;
            s0 += fmaxf(acc[mt][nt][1] + b1v, 0.0f) * r1v;
            s1 += fmaxf(acc[mt][nt][2] + b0v, 0.0f) * r0v;
            s1 += fmaxf(acc[mt][nt][3] + b1v, 0.0f) * r1v;
        }
        s0 += __shfl_xor_sync(0xffffffffu, s0, 1);
        s0 += __shfl_xor_sync(0xffffffffu, s0, 2);
        s1 += __shfl_xor_sync(0xffffffffu, s1, 1);
        s1 += __shfl_xor_sync(0xffffffffu, s1, 2);
        if ((lane & 3) == 0) {
            int row = warp_m * 32 + mt * 16 + (lane >> 2);
            atomicAdd(&s_arr[row], s0);
            atomicAdd(&s_arr[row + 8], s1);
        }
    }
    __syncthreads();

    {
        int bfirst = m0 / 5;
        int blast  = (m0 + 127) / 5;
        int ng = blast - bfirst + 1;
        if (t < ng) {
            int b = bfirst + t;
            float s = 0.0f;
#pragma unroll
            for (int r = 0; r < 5; r++) {
                int m = b * 5 + r;
                if (m >= m0 && m < m0 + 128) s += s_arr[m - m0];
            }
            atomicAdd(&out[br * B + b], s);
        }
    }
}

// ---------------------------------------------------------------------------
extern "C" void kernel_launch(void* const* d_in, const int* in_sizes, int n_in,
                              void* d_out, int out_size)
{
    const float* obs    = (const float*)d_in[0];
    const float* act    = (const float*)d_in[1];
    const float* ag     = (const float*)d_in[2];
    const float* g      = (const float*)d_in[3];
    const float* mp_w   = (const float*)d_in[4];
    const float* mp_b   = (const float*)d_in[5];
    const float* phi_w1 = (const float*)d_in[6];
    const float* phi_b1 = (const float*)d_in[7];
    const float* phi_w2 = (const float*)d_in[8];
    const float* phi_b2 = (const float*)d_in[9];
    const float* phi_w3 = (const float*)d_in[10];
    const float* phi_b3 = (const float*)d_in[11];
    const float* phi_w4 = (const float*)d_in[12];
    const float* phi_b4 = (const float*)d_in[13];
    const float* rho_w1 = (const float*)d_in[14];
    const float* rho_b1 = (const float*)d_in[15];
    const float* rho_w2 = (const float*)d_in[16];
    const float* rho_b2 = (const float*)d_in[17];
    float* out = (float*)d_out;

    const int B = in_sizes[1] / 4;  // act is (B,4)
    const int nrows = B * 5;

    cudaFuncSetAttribute(k_edge_mma, cudaFuncAttributeMaxDynamicSharedMemorySize, E_SMEM);
    cudaFuncSetAttribute(k_phi1_mma, cudaFuncAttributeMaxDynamicSharedMemorySize, P1_SMEM);
    cudaFuncSetAttribute(k_phi2_mma, cudaFuncAttributeMaxDynamicSharedMemorySize, P2_SMEM);

    k_wconv<<<(512 * 160 + 512 * 256 + 255) / 256, 256>>>(phi_w1, phi_w3, phi_w2, phi_w4);
    k_edge_mma<<<B / 16, 640, E_SMEM>>>(obs, act, ag, g, mp_w, mp_b);
    k_phi1_mma<<<dim3(nrows / 128, 4), 256, P1_SMEM>>>(phi_b1, phi_b3);
    k_init<<<(B + 255) / 256, 256>>>(out, rho_b1, rho_b2, B);
    k_phi2_mma<<<dim3(nrows / 128, 2, 2), 256, P2_SMEM>>>(
        phi_b2, phi_b4, rho_w1, rho_w2, out, B);
}

// round 6
// speedup vs baseline: 1.9339x; 1.9339x over previous
#include <cuda_runtime.h>
#include <cuda_bf16.h>
#include <cstdint>

// Problem constants (fixed by setup_inputs)
#define BMAX 16384
#define NROWS_MAX (BMAX * 5)

// ============================================================================
// Scratch (__device__ globals; no allocation allowed)
// ============================================================================
__device__ __nv_bfloat16 g_inp_hi[(size_t)NROWS_MAX * 160];  // 26 MB
__device__ __nv_bfloat16 g_inp_lo[(size_t)NROWS_MAX * 160];
__device__ __nv_bfloat16 g_h_hi[(size_t)NROWS_MAX * 512];    // 84 MB
__device__ __nv_bfloat16 g_h_lo[(size_t)NROWS_MAX * 512];
__device__ __nv_bfloat16 g_w1t_hi[512 * 160], g_w1t_lo[512 * 160];
__device__ __nv_bfloat16 g_w2t_hi[512 * 256], g_w2t_lo[512 * 256];

// ============================================================================
// Warp-MMA helpers (sm_80-era PTX: legal on compute_103, maps to HMMA)
// ============================================================================
#define LDSM_X4(r0, r1, r2, r3, addr) \
    asm volatile("ldmatrix.sync.aligned.m8n8.x4.shared.b16 {%0,%1,%2,%3}, [%4];" \
        : "=r"(r0), "=r"(r1), "=r"(r2), "=r"(r3) : "r"(addr))

__device__ __forceinline__ void mma16816(float* d, const uint32_t* a, const uint32_t* b) {
    asm volatile(
        "mma.sync.aligned.m16n8k16.row.col.f32.bf16.bf16.f32 "
        "{%0,%1,%2,%3}, {%4,%5,%6,%7}, {%8,%9}, {%0,%1,%2,%3};"
        : "+f"(d[0]), "+f"(d[1]), "+f"(d[2]), "+f"(d[3])
        : "r"(a[0]), "r"(a[1]), "r"(a[2]), "r"(a[3]), "r"(b[0]), "r"(b[1]));
}

__device__ __forceinline__ uint32_t smem_u32(const void* p) {
    uint32_t a;
    asm("{ .reg .u64 tmp; cvta.to.shared.u64 tmp, %1; cvt.u32.u64 %0, tmp; }"
        : "=r"(a) : "l"(p));
    return a;
}

__device__ __forceinline__ void split_bf16(float v, __nv_bfloat16& h, __nv_bfloat16& l) {
    h = __float2bfloat16_rn(v);
    l = __float2bfloat16_rn(v - __bfloat162float(h));
}

// ---------------------------------------------------------------------------
// K-edge v2 (factored SIMT): exploit low-rank edge-input structure.
//   inp_mp = [base(14) | dg(2) | src_obj(15) | dst_obj(15)]
//   T_base = base @ W[0:14] + bias       (once per batch, not per edge)
//   T_src[n] = obj_n @ W[16:31]          (5 objects, not 20 edges)
//   T_dst[n] = obj_n @ W[31:46]
//   edge e:  relu(T_base + T_src[src] + T_dst[dst] + dg0*w14 + dg1*w15)
//   agg[dst] += ...  -> g_inp cols 29..156 as bf16 hi/lo
// 8 batches/CTA, 256 threads: bl = t>>5 (batch), nb = t&31 (4 cols).
// Raw features per batch in smem: body 0..9, act 10..13, dg 14..53 (e*2),
// obj 54..128 (n*15); stride 132.
// ---------------------------------------------------------------------------
__global__ __launch_bounds__(256) void k_edge(
    const float* __restrict__ obs, const float* __restrict__ act,
    const float* __restrict__ ag,  const float* __restrict__ g,
    const float* __restrict__ mp_w, const float* __restrict__ mp_b)
{
    extern __shared__ float smem[];
    float* sw   = smem;              // 46*128
    float* sinp = smem + 46 * 128;   // 8*132
    const int t  = threadIdx.x;
    const int b0 = blockIdx.x * 8;

    for (int i = t; i < 46 * 128; i += 256) sw[i] = mp_w[i];

    for (int idx = t; idx < 8 * 129; idx += 256) {
        int bl = idx / 129;
        int j  = idx - bl * 129;
        int b  = b0 + bl;
        float v;
        if (j < 10)       v = obs[b * 85 + j];                    // body
        else if (j < 14)  v = act[b * 4 + (j - 10)];              // act
        else if (j < 54) {                                        // dg pairs
            int e = (j - 14) >> 1;
            int w = (j - 14) & 1;
            v = g[b * 30 + e + w * 10] - ag[b * 30 + e + w * 10];
        } else {                                                  // objects
            v = obs[b * 85 + 10 + (j - 54)];
        }
        sinp[bl * 132 + j] = v;
    }
    __syncthreads();

    const int nb = t & 31;
    const int bl = t >> 5;
    const int n0 = nb * 4;
    const float4* sw4 = reinterpret_cast<const float4*>(sw);
    const float* ip = sinp + bl * 132;

    // T_base (includes bias): base rows 0..13
    float4 tb = *reinterpret_cast<const float4*>(mp_b + n0);
#pragma unroll
    for (int k = 0; k < 14; k++) {
        float  a = ip[k];
        float4 w = sw4[k * 32 + nb];
        tb.x += a * w.x; tb.y += a * w.y; tb.z += a * w.z; tb.w += a * w.w;
    }

    // T_src / T_dst per object: weight rows 16..30 / 31..45
    float ts[5][4], td[5][4];
#pragma unroll
    for (int n = 0; n < 5; n++)
#pragma unroll
        for (int c = 0; c < 4; c++) { ts[n][c] = 0.0f; td[n][c] = 0.0f; }

#pragma unroll
    for (int k = 0; k < 15; k++) {
        float4 ws = sw4[(16 + k) * 32 + nb];
        float4 wd = sw4[(31 + k) * 32 + nb];
#pragma unroll
        for (int n = 0; n < 5; n++) {
            float a = ip[54 + n * 15 + k];
            ts[n][0] += a * ws.x; ts[n][1] += a * ws.y;
            ts[n][2] += a * ws.z; ts[n][3] += a * ws.w;
            td[n][0] += a * wd.x; td[n][1] += a * wd.y;
            td[n][2] += a * wd.z; td[n][3] += a * wd.w;
        }
    }

    const float4 w14 = sw4[14 * 32 + nb];
    const float4 w15 = sw4[15 * 32 + nb];

    float acc[5][4];
#pragma unroll
    for (int i = 0; i < 5; i++)
#pragma unroll
        for (int c = 0; c < 4; c++) acc[i][c] = 0.0f;

#pragma unroll
    for (int e = 0; e < 20; e++) {
        const int src = e >> 2, rr = e & 3;
        const int dst = (rr < src) ? rr : rr + 1;   // compile-time after unroll
        float d0 = ip[14 + e * 2];
        float d1 = ip[15 + e * 2];
        float v0 = tb.x + ts[src][0] + td[dst][0] + d0 * w14.x + d1 * w15.x;
        float v1 = tb.y + ts[src][1] + td[dst][1] + d0 * w14.y + d1 * w15.y;
        float v2 = tb.z + ts[src][2] + td[dst][2] + d0 * w14.z + d1 * w15.z;
        float v3 = tb.w + ts[src][3] + td[dst][3] + d0 * w14.w + d1 * w15.w;
        acc[dst][0] += fmaxf(v0, 0.0f);
        acc[dst][1] += fmaxf(v1, 0.0f);
        acc[dst][2] += fmaxf(v2, 0.0f);
        acc[dst][3] += fmaxf(v3, 0.0f);
    }

    const int b = b0 + bl;
#pragma unroll
    for (int i = 0; i < 5; i++) {
        size_t base = (size_t)(b * 5 + i) * 160 + 29 + n0;
#pragma unroll
        for (int c = 0; c < 4; c++) {
            __nv_bfloat16 h, l;
            split_bf16(acc[i][c], h, l);
            g_inp_hi[base + c] = h;
            g_inp_lo[base + c] = l;
        }
    }
}

// ---------------------------------------------------------------------------
// K-prep: fill g_inp cols 0..28 (act,body,obj) and zero cols 157..159
// ---------------------------------------------------------------------------
__global__ void k_prep(const float* __restrict__ obs, const float* __restrict__ act,
                       int nrows)
{
    int idx = blockIdx.x * 256 + threadIdx.x;
    int row = idx >> 5;
    int c   = idx & 31;
    if (row >= nrows) return;
    int b = row / 5;
    int n = row - b * 5;
    float v; int col;
    if (c < 4)       { v = act[b * 4 + c];                       col = c; }
    else if (c < 14) { v = obs[b * 85 + (c - 4)];                col = c; }
    else if (c < 29) { v = obs[b * 85 + 10 + n * 15 + (c - 14)]; col = c; }
    else             { v = 0.0f;                                  col = 128 + c; } // 157..159
    __nv_bfloat16 h, l;
    split_bf16(v, h, l);
    g_inp_hi[(size_t)row * 160 + col] = h;
    g_inp_lo[(size_t)row * 160 + col] = l;
}

// ---------------------------------------------------------------------------
// K-wconv: transpose + bf16-split weights.
// ---------------------------------------------------------------------------
__global__ void k_wconv(const float* __restrict__ w1, const float* __restrict__ w3,
                        const float* __restrict__ w2, const float* __restrict__ w4)
{
    int idx = blockIdx.x * 256 + threadIdx.x;
    const int N1 = 512 * 160;
    const int N2 = 512 * 256;
    if (idx < N1) {
        int n = idx / 160, k = idx - n * 160;
        float v = 0.0f;
        if (k < 157) v = (n < 256) ? w1[k * 256 + n] : w3[k * 256 + (n - 256)];
        __nv_bfloat16 h, l;
        split_bf16(v, h, l);
        g_w1t_hi[idx] = h; g_w1t_lo[idx] = l;
    } else if (idx < N1 + N2) {
        int j = idx - N1;
        int n = j / 256, k = j - n * 256;
        float v = (n < 256) ? w2[k * 256 + n] : w4[k * 256 + (n - 256)];
        __nv_bfloat16 h, l;
        split_bf16(v, h, l);
        g_w2t_hi[j] = h; g_w2t_lo[j] = l;
    }
}

// ---------------------------------------------------------------------------
// K-init: out[b] = rho_b
// ---------------------------------------------------------------------------
__global__ void k_init(float* __restrict__ out,
                       const float* __restrict__ rb1, const float* __restrict__ rb2, int B)
{
    int i = blockIdx.x * 256 + threadIdx.x;
    if (i < B) { out[i] = rb1[0]; out[B + i] = rb2[0]; }
}

// ---------------------------------------------------------------------------
// K-phi1 (MMA): D[128m x 128n] = inp-tile @ w1t-block, K=160 (5 chunks of 32).
// ---------------------------------------------------------------------------
#define P1_BIAS 0
#define P1_AHI  512
#define P1_ALO  10752
#define P1_BHI  20992
#define P1_BLO  31232
#define P1_SMEM 41472

__global__ __launch_bounds__(256, 2) void k_phi1_mma(
    const float* __restrict__ phi_b1, const float* __restrict__ phi_b3)
{
    extern __shared__ char smemc[];
    const uint32_t sbase = smem_u32(smemc);
    const int t    = threadIdx.x;
    const int wid  = t >> 5;
    const int lane = t & 31;
    const int m0   = blockIdx.x * 128;
    const int nc   = blockIdx.y;            // which 128 of N=512

    float* sb = reinterpret_cast<float*>(smemc + P1_BIAS);
    if (t < 128) {
        int n = nc * 128 + t;
        sb[t] = (n < 256) ? phi_b1[n] : phi_b3[n - 256];
    }

    const int warp_m = wid & 3;
    const int warp_n = wid >> 2;

    float acc[2][8][4];
#pragma unroll
    for (int mt = 0; mt < 2; mt++)
#pragma unroll
        for (int nt = 0; nt < 8; nt++)
#pragma unroll
            for (int j = 0; j < 4; j++) acc[mt][nt][j] = 0.0f;

    const int a_row  = warp_m * 32 + (lane & 15);
    const int a_ksub = (lane >> 4) * 8;
    const int b_row  = warp_n * 64 + (lane & 7) + ((lane >> 4) & 1) * 8;
    const int b_ksub = ((lane >> 3) & 1) * 8;

    for (int kc = 0; kc < 5; kc++) {
        __syncthreads();
        for (int idx = t; idx < 128 * 4; idx += 256) {
            int row = idx >> 2, q = idx & 3;
            const uint4* sh = reinterpret_cast<const uint4*>(
                g_inp_hi + (size_t)(m0 + row) * 160 + kc * 32) + q;
            const uint4* sl = reinterpret_cast<const uint4*>(
                g_inp_lo + (size_t)(m0 + row) * 160 + kc * 32) + q;
            *reinterpret_cast<uint4*>(smemc + P1_AHI + row * 80 + q * 16) = *sh;
            *reinterpret_cast<uint4*>(smemc + P1_ALO + row * 80 + q * 16) = *sl;
        }
        for (int idx = t; idx < 128 * 4; idx += 256) {
            int n = idx >> 2, q = idx & 3;
            const uint4* sh = reinterpret_cast<const uint4*>(
                g_w1t_hi + (size_t)(nc * 128 + n) * 160 + kc * 32) + q;
            const uint4* sl = reinterpret_cast<const uint4*>(
                g_w1t_lo + (size_t)(nc * 128 + n) * 160 + kc * 32) + q;
            *reinterpret_cast<uint4*>(smemc + P1_BHI + n * 80 + q * 16) = *sh;
            *reinterpret_cast<uint4*>(smemc + P1_BLO + n * 80 + q * 16) = *sl;
        }
        __syncthreads();

#pragma unroll
        for (int ks = 0; ks < 2; ks++) {
            const uint32_t a_off = (uint32_t)(a_row * 80 + (ks * 16 + a_ksub) * 2);
            const uint32_t b_off = (uint32_t)(b_row * 80 + (ks * 16 + b_ksub) * 2);
            uint32_t ahi[2][4], alo[2][4];
#pragma unroll
            for (int mt = 0; mt < 2; mt++) {
                LDSM_X4(ahi[mt][0], ahi[mt][1], ahi[mt][2], ahi[mt][3],
                        sbase + P1_AHI + a_off + mt * 16 * 80);
                LDSM_X4(alo[mt][0], alo[mt][1], alo[mt][2], alo[mt][3],
                        sbase + P1_ALO + a_off + mt * 16 * 80);
            }
#pragma unroll
            for (int p = 0; p < 4; p++) {
                uint32_t bh[4], bl[4];
                LDSM_X4(bh[0], bh[1], bh[2], bh[3],
                        sbase + P1_BHI + b_off + p * 16 * 80);
                LDSM_X4(bl[0], bl[1], bl[2], bl[3],
                        sbase + P1_BLO + b_off + p * 16 * 80);
#pragma unroll
                for (int mt = 0; mt < 2; mt++)
#pragma unroll
                    for (int hh = 0; hh < 2; hh++) {
                        mma16816(acc[mt][p * 2 + hh], ahi[mt], &bh[hh * 2]);
                        mma16816(acc[mt][p * 2 + hh], ahi[mt], &bl[hh * 2]);
                        mma16816(acc[mt][p * 2 + hh], alo[mt], &bh[hh * 2]);
                    }
            }
        }
    }

#pragma unroll
    for (int mt = 0; mt < 2; mt++)
#pragma unroll
        for (int nt = 0; nt < 8; nt++) {
            int c = warp_n * 64 + nt * 8 + (lane & 3) * 2;
            float b0 = sb[c], b1 = sb[c + 1];
#pragma unroll
            for (int half = 0; half < 2; half++) {
                int row = warp_m * 32 + mt * 16 + (lane >> 2) + half * 8;
                float v0 = fmaxf(acc[mt][nt][half * 2]     + b0, 0.0f);
                float v1 = fmaxf(acc[mt][nt][half * 2 + 1] + b1, 0.0f);
                __nv_bfloat16 h0, l0, h1, l1;
                split_bf16(v0, h0, l0);
                split_bf16(v1, h1, l1);
                uint32_t ph = ((uint32_t)__bfloat16_as_ushort(h1) << 16) | __bfloat16_as_ushort(h0);
                uint32_t pl = ((uint32_t)__bfloat16_as_ushort(l1) << 16) | __bfloat16_as_ushort(l0);
                size_t off = (size_t)(m0 + row) * 512 + nc * 128 + c;
                *reinterpret_cast<uint32_t*>(g_h_hi + off) = ph;
                *reinterpret_cast<uint32_t*>(g_h_lo + off) = pl;
            }
        }
}

// ---------------------------------------------------------------------------
// K-phi2 (MMA): D[128m x 128n] = h-tile @ w2t-block, K=256 (4 chunks of 64).
// ---------------------------------------------------------------------------
#define SB_BIAS 0
#define SB_RHO  512
#define SB_SARR 1024
#define SB_AHI  1536
#define SB_ALO  19968
#define SB_BHI  38400
#define SB_BLO  56832
#define P2_SMEM 75264

__global__ __launch_bounds__(256, 2) void k_phi2_mma(
    const float* __restrict__ phi_b2, const float* __restrict__ phi_b4,
    const float* __restrict__ rho_w1, const float* __restrict__ rho_w2,
    float* __restrict__ out, int B)
{
    extern __shared__ char smemc[];
    const uint32_t sbase = smem_u32(smemc);
    const int t    = threadIdx.x;
    const int wid  = t >> 5;
    const int lane = t & 31;
    const int m0   = blockIdx.x * 128;
    const int br   = blockIdx.y;
    const int nc   = blockIdx.z;

    const float* bias = br ? phi_b4 : phi_b2;
    const float* rho  = br ? rho_w2 : rho_w1;

    float* sb    = reinterpret_cast<float*>(smemc + SB_BIAS);
    float* sr    = reinterpret_cast<float*>(smemc + SB_RHO);
    float* s_arr = reinterpret_cast<float*>(smemc + SB_SARR);

    if (t < 128) {
        sb[t] = bias[nc * 128 + t];
        sr[t] = rho[nc * 128 + t];
        s_arr[t] = 0.0f;
    }

    const int warp_m = wid & 3;
    const int warp_n = wid >> 2;

    float acc[2][8][4];
#pragma unroll
    for (int mt = 0; mt < 2; mt++)
#pragma unroll
        for (int nt = 0; nt < 8; nt++)
#pragma unroll
            for (int j = 0; j < 4; j++) acc[mt][nt][j] = 0.0f;

    const int a_row  = warp_m * 32 + (lane & 15);
    const int a_ksub = (lane >> 4) * 8;
    const int b_row  = warp_n * 64 + (lane & 7) + ((lane >> 4) & 1) * 8;
    const int b_ksub = ((lane >> 3) & 1) * 8;

    for (int kc = 0; kc < 4; kc++) {
        __syncthreads();
        for (int idx = t; idx < 128 * 8; idx += 256) {
            int row = idx >> 3, q = idx & 7;
            const uint4* sh = reinterpret_cast<const uint4*>(
                g_h_hi + (size_t)(m0 + row) * 512 + br * 256 + kc * 64) + q;
            const uint4* sl = reinterpret_cast<const uint4*>(
                g_h_lo + (size_t)(m0 + row) * 512 + br * 256 + kc * 64) + q;
            *reinterpret_cast<uint4*>(smemc + SB_AHI + row * 144 + q * 16) = *sh;
            *reinterpret_cast<uint4*>(smemc + SB_ALO + row * 144 + q * 16) = *sl;
        }
        for (int idx = t; idx < 128 * 8; idx += 256) {
            int n = idx >> 3, q = idx & 7;
            const uint4* sh = reinterpret_cast<const uint4*>(
                g_w2t_hi + (size_t)(br * 256 + nc * 128 + n) * 256 + kc * 64) + q;
            const uint4* sl = reinterpret_cast<const uint4*>(
                g_w2t_lo + (size_t)(br * 256 + nc * 128 + n) * 256 + kc * 64) + q;
            *reinterpret_cast<uint4*>(smemc + SB_BHI + n * 144 + q * 16) = *sh;
            *reinterpret_cast<uint4*>(smemc + SB_BLO + n * 144 + q * 16) = *sl;
        }
        __syncthreads();

#pragma unroll
        for (int ks = 0; ks < 4; ks++) {
            const uint32_t a_off = (uint32_t)(a_row * 144 + (ks * 16 + a_ksub) * 2);
            const uint32_t b_off = (uint32_t)(b_row * 144 + (ks * 16 + b_ksub) * 2);
            uint32_t ahi[2][4], alo[2][4];
#pragma unroll
            for (int mt = 0; mt < 2; mt++) {
                LDSM_X4(ahi[mt][0], ahi[mt][1], ahi[mt][2], ahi[mt][3],
                        sbase + SB_AHI + a_off + mt * 16 * 144);
                LDSM_X4(alo[mt][0], alo[mt][1], alo[mt][2], alo[mt][3],
                        sbase + SB_ALO + a_off + mt * 16 * 144);
            }
#pragma unroll
            for (int p = 0; p < 4; p++) {
                uint32_t bh[4], bl[4];
                LDSM_X4(bh[0], bh[1], bh[2], bh[3],
                        sbase + SB_BHI + b_off + p * 16 * 144);
                LDSM_X4(bl[0], bl[1], bl[2], bl[3],
                        sbase + SB_BLO + b_off + p * 16 * 144);
#pragma unroll
                for (int mt = 0; mt < 2; mt++)
#pragma unroll
                    for (int hh = 0; hh < 2; hh++) {
                        mma16816(acc[mt][p * 2 + hh], ahi[mt], &bh[hh * 2]);
                        mma16816(acc[mt][p * 2 + hh], ahi[mt], &bl[hh * 2]);
                        mma16816(acc[mt][p * 2 + hh], alo[mt], &bh[hh * 2]);
                    }
            }
        }
    }

#pragma unroll
    for (int mt = 0; mt < 2; mt++) {
        float s0 = 0.0f, s1 = 0.0f;
#pragma unroll
        for (int nt = 0; nt < 8; nt++) {
            int c = warp_n * 64 + nt * 8 + (lane & 3) * 2;
            float b0v = sb[c], b1v = sb[c + 1];
            float r0v = sr[c], r1v = sr[c + 1];
            s0 += fmaxf(acc[mt][nt][0] + b0v, 0.0f) * r0v;
            s0 += fmaxf(acc[mt][nt][1] + b1v, 0.0f) * r1v;
            s1 += fmaxf(acc[mt][nt][2] + b0v, 0.0f) * r0v;
            s1 += fmaxf(acc[mt][nt][3] + b1v, 0.0f) * r1v;
        }
        s0 += __shfl_xor_sync(0xffffffffu, s0, 1);
        s0 += __shfl_xor_sync(0xffffffffu, s0, 2);
        s1 += __shfl_xor_sync(0xffffffffu, s1, 1);
        s1 += __shfl_xor_sync(0xffffffffu, s1, 2);
        if ((lane & 3) == 0) {
            int row = warp_m * 32 + mt * 16 + (lane >> 2);
            atomicAdd(&s_arr[row], s0);
            atomicAdd(&s_arr[row + 8], s1);
        }
    }
    __syncthreads();

    {
        int bfirst = m0 / 5;
        int blast  = (m0 + 127) / 5;
        int ng = blast - bfirst + 1;
        if (t < ng) {
            int b = bfirst + t;
            float s = 0.0f;
#pragma unroll
            for (int r = 0; r < 5; r++) {
                int m = b * 5 + r;
                if (m >= m0 && m < m0 + 128) s += s_arr[m - m0];
            }
            atomicAdd(&out[br * B + b], s);
        }
    }
}

// ---------------------------------------------------------------------------
extern "C" void kernel_launch(void* const* d_in, const int* in_sizes, int n_in,
                              void* d_out, int out_size)
{
    const float* obs    = (const float*)d_in[0];
    const float* act    = (const float*)d_in[1];
    const float* ag     = (const float*)d_in[2];
    const float* g      = (const float*)d_in[3];
    const float* mp_w   = (const float*)d_in[4];
    const float* mp_b   = (const float*)d_in[5];
    const float* phi_w1 = (const float*)d_in[6];
    const float* phi_b1 = (const float*)d_in[7];
    const float* phi_w2 = (const float*)d_in[8];
    const float* phi_b2 = (const float*)d_in[9];
    const float* phi_w3 = (const float*)d_in[10];
    const float* phi_b3 = (const float*)d_in[11];
    const float* phi_w4 = (const float*)d_in[12];
    const float* phi_b4 = (const float*)d_in[13];
    const float* rho_w1 = (const float*)d_in[14];
    const float* rho_b1 = (const float*)d_in[15];
    const float* rho_w2 = (const float*)d_in[16];
    const float* rho_b2 = (const float*)d_in[17];
    float* out = (float*)d_out;

    const int B = in_sizes[1] / 4;  // act is (B,4)
    const int nrows = B * 5;

    const int S1 = (46 * 128 + 8 * 132) * 4;   // 27,776 B
    cudaFuncSetAttribute(k_edge, cudaFuncAttributeMaxDynamicSharedMemorySize, S1);
    cudaFuncSetAttribute(k_phi1_mma, cudaFuncAttributeMaxDynamicSharedMemorySize, P1_SMEM);
    cudaFuncSetAttribute(k_phi2_mma, cudaFuncAttributeMaxDynamicSharedMemorySize, P2_SMEM);

    k_wconv<<<(512 * 160 + 512 * 256 + 255) / 256, 256>>>(phi_w1, phi_w3, phi_w2, phi_w4);
    k_edge<<<B / 8, 256, S1>>>(obs, act, ag, g, mp_w, mp_b);
    k_prep<<<(nrows * 32 + 255) / 256, 256>>>(obs, act, nrows);
    k_phi1_mma<<<dim3(nrows / 128, 4), 256, P1_SMEM>>>(phi_b1, phi_b3);
    k_init<<<(B + 255) / 256, 256>>>(out, rho_b1, rho_b2, B);
    k_phi2_mma<<<dim3(nrows / 128, 2, 2), 256, P2_SMEM>>>(
        phi_b2, phi_b4, rho_w1, rho_w2, out, B);
}

// round 7
// speedup vs baseline: 2.3467x; 1.2134x over previous
#include <cuda_runtime.h>
#include <cuda_bf16.h>
#include <cstdint>

// Problem constants (fixed by setup_inputs)
#define BMAX 16384
#define NROWS_MAX (BMAX * 5)

// ============================================================================
// Scratch (__device__ globals; no allocation allowed)
// ============================================================================
__device__ __nv_bfloat16 g_inp_hi[(size_t)NROWS_MAX * 160];  // 26 MB
__device__ __nv_bfloat16 g_inp_lo[(size_t)NROWS_MAX * 160];
__device__ __nv_bfloat16 g_h_hi[(size_t)NROWS_MAX * 512];    // 84 MB
__device__ __nv_bfloat16 g_h_lo[(size_t)NROWS_MAX * 512];
__device__ __nv_bfloat16 g_w1t_hi[512 * 160], g_w1t_lo[512 * 160];
__device__ __nv_bfloat16 g_w2t_hi[512 * 256], g_w2t_lo[512 * 256];

// ============================================================================
// Warp-MMA + cp.async helpers (sm_80-era PTX: legal on compute_103)
// ============================================================================
#define LDSM_X4(r0, r1, r2, r3, addr) \
    asm volatile("ldmatrix.sync.aligned.m8n8.x4.shared.b16 {%0,%1,%2,%3}, [%4];" \
        : "=r"(r0), "=r"(r1), "=r"(r2), "=r"(r3) : "r"(addr))

__device__ __forceinline__ void mma16816(float* d, const uint32_t* a, const uint32_t* b) {
    asm volatile(
        "mma.sync.aligned.m16n8k16.row.col.f32.bf16.bf16.f32 "
        "{%0,%1,%2,%3}, {%4,%5,%6,%7}, {%8,%9}, {%0,%1,%2,%3};"
        : "+f"(d[0]), "+f"(d[1]), "+f"(d[2]), "+f"(d[3])
        : "r"(a[0]), "r"(a[1]), "r"(a[2]), "r"(a[3]), "r"(b[0]), "r"(b[1]));
}

__device__ __forceinline__ uint32_t smem_u32(const void* p) {
    uint32_t a;
    asm("{ .reg .u64 tmp; cvta.to.shared.u64 tmp, %1; cvt.u32.u64 %0, tmp; }"
        : "=r"(a) : "l"(p));
    return a;
}

#define CP_ASYNC16(dst, src) \
    asm volatile("cp.async.ca.shared.global [%0], [%1], 16;" :: "r"(dst), "l"(src))
#define CP_COMMIT() asm volatile("cp.async.commit_group;" ::: "memory")
#define CP_WAIT(n)  asm volatile("cp.async.wait_group %0;" :: "n"(n) : "memory")

__device__ __forceinline__ void split_bf16(float v, __nv_bfloat16& h, __nv_bfloat16& l) {
    h = __float2bfloat16_rn(v);
    l = __float2bfloat16_rn(v - __bfloat162float(h));
}

// Stage a 128-row x 32-col bf16 tile (row stride gstride elems) into smem
// with 80B row stride, via 16B cp.async. 512 copies / 256 threads.
__device__ __forceinline__ void stage128x32(
    uint32_t sdst, const __nv_bfloat16* __restrict__ gsrc, int gstride, int t)
{
#pragma unroll
    for (int i = 0; i < 2; i++) {
        int idx = t + i * 256;
        int row = idx >> 2, q = idx & 3;
        CP_ASYNC16(sdst + row * 80 + q * 16, gsrc + (size_t)row * gstride + q * 8);
    }
}

// ---------------------------------------------------------------------------
// K-edge (factored SIMT) — unchanged from R6 (validated)
// ---------------------------------------------------------------------------
__global__ __launch_bounds__(256) void k_edge(
    const float* __restrict__ obs, const float* __restrict__ act,
    const float* __restrict__ ag,  const float* __restrict__ g,
    const float* __restrict__ mp_w, const float* __restrict__ mp_b)
{
    extern __shared__ float smem[];
    float* sw   = smem;              // 46*128
    float* sinp = smem + 46 * 128;   // 8*132
    const int t  = threadIdx.x;
    const int b0 = blockIdx.x * 8;

    for (int i = t; i < 46 * 128; i += 256) sw[i] = mp_w[i];

    for (int idx = t; idx < 8 * 129; idx += 256) {
        int bl = idx / 129;
        int j  = idx - bl * 129;
        int b  = b0 + bl;
        float v;
        if (j < 10)       v = obs[b * 85 + j];
        else if (j < 14)  v = act[b * 4 + (j - 10)];
        else if (j < 54) {
            int e = (j - 14) >> 1;
            int w = (j - 14) & 1;
            v = g[b * 30 + e + w * 10] - ag[b * 30 + e + w * 10];
        } else {
            v = obs[b * 85 + 10 + (j - 54)];
        }
        sinp[bl * 132 + j] = v;
    }
    __syncthreads();

    const int nb = t & 31;
    const int bl = t >> 5;
    const int n0 = nb * 4;
    const float4* sw4 = reinterpret_cast<const float4*>(sw);
    const float* ip = sinp + bl * 132;

    float4 tb = *reinterpret_cast<const float4*>(mp_b + n0);
#pragma unroll
    for (int k = 0; k < 14; k++) {
        float  a = ip[k];
        float4 w = sw4[k * 32 + nb];
        tb.x += a * w.x; tb.y += a * w.y; tb.z += a * w.z; tb.w += a * w.w;
    }

    float ts[5][4], td[5][4];
#pragma unroll
    for (int n = 0; n < 5; n++)
#pragma unroll
        for (int c = 0; c < 4; c++) { ts[n][c] = 0.0f; td[n][c] = 0.0f; }

#pragma unroll
    for (int k = 0; k < 15; k++) {
        float4 ws = sw4[(16 + k) * 32 + nb];
        float4 wd = sw4[(31 + k) * 32 + nb];
#pragma unroll
        for (int n = 0; n < 5; n++) {
            float a = ip[54 + n * 15 + k];
            ts[n][0] += a * ws.x; ts[n][1] += a * ws.y;
            ts[n][2] += a * ws.z; ts[n][3] += a * ws.w;
            td[n][0] += a * wd.x; td[n][1] += a * wd.y;
            td[n][2] += a * wd.z; td[n][3] += a * wd.w;
        }
    }

    const float4 w14 = sw4[14 * 32 + nb];
    const float4 w15 = sw4[15 * 32 + nb];

    float acc[5][4];
#pragma unroll
    for (int i = 0; i < 5; i++)
#pragma unroll
        for (int c = 0; c < 4; c++) acc[i][c] = 0.0f;

#pragma unroll
    for (int e = 0; e < 20; e++) {
        const int src = e >> 2, rr = e & 3;
        const int dst = (rr < src) ? rr : rr + 1;
        float d0 = ip[14 + e * 2];
        float d1 = ip[15 + e * 2];
        float v0 = tb.x + ts[src][0] + td[dst][0] + d0 * w14.x + d1 * w15.x;
        float v1 = tb.y + ts[src][1] + td[dst][1] + d0 * w14.y + d1 * w15.y;
        float v2 = tb.z + ts[src][2] + td[dst][2] + d0 * w14.z + d1 * w15.z;
        float v3 = tb.w + ts[src][3] + td[dst][3] + d0 * w14.w + d1 * w15.w;
        acc[dst][0] += fmaxf(v0, 0.0f);
        acc[dst][1] += fmaxf(v1, 0.0f);
        acc[dst][2] += fmaxf(v2, 0.0f);
        acc[dst][3] += fmaxf(v3, 0.0f);
    }

    const int b = b0 + bl;
#pragma unroll
    for (int i = 0; i < 5; i++) {
        size_t base = (size_t)(b * 5 + i) * 160 + 29 + n0;
#pragma unroll
        for (int c = 0; c < 4; c++) {
            __nv_bfloat16 h, l;
            split_bf16(acc[i][c], h, l);
            g_inp_hi[base + c] = h;
            g_inp_lo[base + c] = l;
        }
    }
}

// ---------------------------------------------------------------------------
// K-prep: fill g_inp cols 0..28 and zero cols 157..159
// ---------------------------------------------------------------------------
__global__ void k_prep(const float* __restrict__ obs, const float* __restrict__ act,
                       int nrows)
{
    int idx = blockIdx.x * 256 + threadIdx.x;
    int row = idx >> 5;
    int c   = idx & 31;
    if (row >= nrows) return;
    int b = row / 5;
    int n = row - b * 5;
    float v; int col;
    if (c < 4)       { v = act[b * 4 + c];                       col = c; }
    else if (c < 14) { v = obs[b * 85 + (c - 4)];                col = c; }
    else if (c < 29) { v = obs[b * 85 + 10 + n * 15 + (c - 14)]; col = c; }
    else             { v = 0.0f;                                  col = 128 + c; }
    __nv_bfloat16 h, l;
    split_bf16(v, h, l);
    g_inp_hi[(size_t)row * 160 + col] = h;
    g_inp_lo[(size_t)row * 160 + col] = l;
}

// ---------------------------------------------------------------------------
// K-wconv: transpose + bf16-split weights.
// ---------------------------------------------------------------------------
__global__ void k_wconv(const float* __restrict__ w1, const float* __restrict__ w3,
                        const float* __restrict__ w2, const float* __restrict__ w4)
{
    int idx = blockIdx.x * 256 + threadIdx.x;
    const int N1 = 512 * 160;
    const int N2 = 512 * 256;
    if (idx < N1) {
        int n = idx / 160, k = idx - n * 160;
        float v = 0.0f;
        if (k < 157) v = (n < 256) ? w1[k * 256 + n] : w3[k * 256 + (n - 256)];
        __nv_bfloat16 h, l;
        split_bf16(v, h, l);
        g_w1t_hi[idx] = h; g_w1t_lo[idx] = l;
    } else if (idx < N1 + N2) {
        int j = idx - N1;
        int n = j / 256, k = j - n * 256;
        float v = (n < 256) ? w2[k * 256 + n] : w4[k * 256 + (n - 256)];
        __nv_bfloat16 h, l;
        split_bf16(v, h, l);
        g_w2t_hi[j] = h; g_w2t_lo[j] = l;
    }
}

// ---------------------------------------------------------------------------
// K-init: out[b] = rho_b
// ---------------------------------------------------------------------------
__global__ void k_init(float* __restrict__ out,
                       const float* __restrict__ rb1, const float* __restrict__ rb2, int B)
{
    int i = blockIdx.x * 256 + threadIdx.x;
    if (i < B) { out[i] = rb1[0]; out[B + i] = rb2[0]; }
}

// ---------------------------------------------------------------------------
// Shared smem layout for the two pipelined MMA kernels.
//   bias 0..512, rho 512..1024, s_arr 1024..1536,
//   2 buffers x { A_hi, A_lo, B_hi, B_lo } each 128x80B = 10240B.
// ---------------------------------------------------------------------------
#define PP_BIAS  0
#define PP_RHO   512
#define PP_SARR  1024
#define PP_BUF   1536
#define PP_TILE  10240
#define PP_BUFSZ (4 * PP_TILE)          // 40960
#define PP_SMEM  (PP_BUF + 2 * PP_BUFSZ) // 83456

// Compute one 32-K chunk (2 ksteps) from buffer bb into acc.
#define CHUNK_COMPUTE(bb)                                                       \
    do {                                                                        \
        const uint32_t base_ = sbase + PP_BUF + (bb) * PP_BUFSZ;                \
        _Pragma("unroll")                                                       \
        for (int ks = 0; ks < 2; ks++) {                                        \
            const uint32_t a_off = (uint32_t)(a_row * 80 + (ks * 16 + a_ksub) * 2); \
            const uint32_t b_off = (uint32_t)(b_row * 80 + (ks * 16 + b_ksub) * 2); \
            uint32_t ahi[2][4], alo[2][4];                                      \
            _Pragma("unroll")                                                   \
            for (int mt = 0; mt < 2; mt++) {                                    \
                LDSM_X4(ahi[mt][0], ahi[mt][1], ahi[mt][2], ahi[mt][3],         \
                        base_ + 0 * PP_TILE + a_off + mt * 16 * 80);            \
                LDSM_X4(alo[mt][0], alo[mt][1], alo[mt][2], alo[mt][3],         \
                        base_ + 1 * PP_TILE + a_off + mt * 16 * 80);            \
            }                                                                   \
            _Pragma("unroll")                                                   \
            for (int p = 0; p < 4; p++) {                                       \
                uint32_t bh[4], bl[4];                                          \
                LDSM_X4(bh[0], bh[1], bh[2], bh[3],                             \
                        base_ + 2 * PP_TILE + b_off + p * 16 * 80);             \
                LDSM_X4(bl[0], bl[1], bl[2], bl[3],                             \
                        base_ + 3 * PP_TILE + b_off + p * 16 * 80);             \
                _Pragma("unroll")                                               \
                for (int mt = 0; mt < 2; mt++)                                  \
                    _Pragma("unroll")                                           \
                    for (int hh = 0; hh < 2; hh++) {                            \
                        mma16816(acc[mt][p * 2 + hh], ahi[mt], &bh[hh * 2]);    \
                        mma16816(acc[mt][p * 2 + hh], ahi[mt], &bl[hh * 2]);    \
                        mma16816(acc[mt][p * 2 + hh], alo[mt], &bh[hh * 2]);    \
                    }                                                           \
            }                                                                   \
        }                                                                       \
    } while (0)

#define STAGE_CHUNK(bb, kc)                                                     \
    do {                                                                        \
        uint32_t sd_ = sbase + PP_BUF + (bb) * PP_BUFSZ;                        \
        stage128x32(sd_ + 0 * PP_TILE, Ahi_src + (kc) * 32, a_stride, t);       \
        stage128x32(sd_ + 1 * PP_TILE, Alo_src + (kc) * 32, a_stride, t);       \
        stage128x32(sd_ + 2 * PP_TILE, Bhi_src + (kc) * 32, b_stride, t);       \
        stage128x32(sd_ + 3 * PP_TILE, Blo_src + (kc) * 32, b_stride, t);       \
        CP_COMMIT();                                                            \
    } while (0)

// ---------------------------------------------------------------------------
// K-phi1 (MMA, cp.async double-buffered): K=160, 5 chunks of 32.
// ---------------------------------------------------------------------------
__global__ __launch_bounds__(256, 2) void k_phi1_mma(
    const float* __restrict__ phi_b1, const float* __restrict__ phi_b3)
{
    extern __shared__ char smemc[];
    const uint32_t sbase = smem_u32(smemc);
    const int t    = threadIdx.x;
    const int wid  = t >> 5;
    const int lane = t & 31;
    const int m0   = blockIdx.x * 128;
    const int nc   = blockIdx.y;            // which 128 of N=512

    float* sb = reinterpret_cast<float*>(smemc + PP_BIAS);
    if (t < 128) {
        int n = nc * 128 + t;
        sb[t] = (n < 256) ? phi_b1[n] : phi_b3[n - 256];
    }

    const __nv_bfloat16* Ahi_src = g_inp_hi + (size_t)m0 * 160;
    const __nv_bfloat16* Alo_src = g_inp_lo + (size_t)m0 * 160;
    const __nv_bfloat16* Bhi_src = g_w1t_hi + (size_t)(nc * 128) * 160;
    const __nv_bfloat16* Blo_src = g_w1t_lo + (size_t)(nc * 128) * 160;
    const int a_stride = 160, b_stride = 160;

    const int warp_m = wid & 3;
    const int warp_n = wid >> 2;

    float acc[2][8][4];
#pragma unroll
    for (int mt = 0; mt < 2; mt++)
#pragma unroll
        for (int nt = 0; nt < 8; nt++)
#pragma unroll
            for (int j = 0; j < 4; j++) acc[mt][nt][j] = 0.0f;

    const int a_row  = warp_m * 32 + (lane & 15);
    const int a_ksub = (lane >> 4) * 8;
    const int b_row  = warp_n * 64 + (lane & 7) + ((lane >> 4) & 1) * 8;
    const int b_ksub = ((lane >> 3) & 1) * 8;

    STAGE_CHUNK(0, 0);
#pragma unroll
    for (int kc = 0; kc < 5; kc++) {
        if (kc < 4) {
            STAGE_CHUNK((kc + 1) & 1, kc + 1);
            CP_WAIT(1);
        } else {
            CP_WAIT(0);
        }
        __syncthreads();
        CHUNK_COMPUTE(kc & 1);
        __syncthreads();
    }

    // epilogue: relu(+bias), split to hi/lo bf16, store to g_h
#pragma unroll
    for (int mt = 0; mt < 2; mt++)
#pragma unroll
        for (int nt = 0; nt < 8; nt++) {
            int c = warp_n * 64 + nt * 8 + (lane & 3) * 2;
            float b0 = sb[c], b1 = sb[c + 1];
#pragma unroll
            for (int half = 0; half < 2; half++) {
                int row = warp_m * 32 + mt * 16 + (lane >> 2) + half * 8;
                float v0 = fmaxf(acc[mt][nt][half * 2]     + b0, 0.0f);
                float v1 = fmaxf(acc[mt][nt][half * 2 + 1] + b1, 0.0f);
                __nv_bfloat16 h0, l0, h1, l1;
                split_bf16(v0, h0, l0);
                split_bf16(v1, h1, l1);
                uint32_t ph = ((uint32_t)__bfloat16_as_ushort(h1) << 16) | __bfloat16_as_ushort(h0);
                uint32_t pl = ((uint32_t)__bfloat16_as_ushort(l1) << 16) | __bfloat16_as_ushort(l0);
                size_t off = (size_t)(m0 + row) * 512 + nc * 128 + c;
                *reinterpret_cast<uint32_t*>(g_h_hi + off) = ph;
                *reinterpret_cast<uint32_t*>(g_h_lo + off) = pl;
            }
        }
}

// ---------------------------------------------------------------------------
// K-phi2 (MMA, cp.async double-buffered): K=256, 8 chunks of 32.
// Fused epilogue: q += sum relu(D+bias)*rho -> atomicAdd per b.
// ---------------------------------------------------------------------------
__global__ __launch_bounds__(256, 2) void k_phi2_mma(
    const float* __restrict__ phi_b2, const float* __restrict__ phi_b4,
    const float* __restrict__ rho_w1, const float* __restrict__ rho_w2,
    float* __restrict__ out, int B)
{
    extern __shared__ char smemc[];
    const uint32_t sbase = smem_u32(smemc);
    const int t    = threadIdx.x;
    const int wid  = t >> 5;
    const int lane = t & 31;
    const int m0   = blockIdx.x * 128;
    const int br   = blockIdx.y;
    const int nc   = blockIdx.z;

    const float* bias = br ? phi_b4 : phi_b2;
    const float* rho  = br ? rho_w2 : rho_w1;

    float* sb    = reinterpret_cast<float*>(smemc + PP_BIAS);
    float* sr    = reinterpret_cast<float*>(smemc + PP_RHO);
    float* s_arr = reinterpret_cast<float*>(smemc + PP_SARR);

    if (t < 128) {
        sb[t] = bias[nc * 128 + t];
        sr[t] = rho[nc * 128 + t];
        s_arr[t] = 0.0f;
    }

    const __nv_bfloat16* Ahi_src = g_h_hi + (size_t)m0 * 512 + br * 256;
    const __nv_bfloat16* Alo_src = g_h_lo + (size_t)m0 * 512 + br * 256;
    const __nv_bfloat16* Bhi_src = g_w2t_hi + (size_t)(br * 256 + nc * 128) * 256;
    const __nv_bfloat16* Blo_src = g_w2t_lo + (size_t)(br * 256 + nc * 128) * 256;
    const int a_stride = 512, b_stride = 256;

    const int warp_m = wid & 3;
    const int warp_n = wid >> 2;

    float acc[2][8][4];
#pragma unroll
    for (int mt = 0; mt < 2; mt++)
#pragma unroll
        for (int nt = 0; nt < 8; nt++)
#pragma unroll
            for (int j = 0; j < 4; j++) acc[mt][nt][j] = 0.0f;

    const int a_row  = warp_m * 32 + (lane & 15);
    const int a_ksub = (lane >> 4) * 8;
    const int b_row  = warp_n * 64 + (lane & 7) + ((lane >> 4) & 1) * 8;
    const int b_ksub = ((lane >> 3) & 1) * 8;

    STAGE_CHUNK(0, 0);
#pragma unroll
    for (int kc = 0; kc < 8; kc++) {
        if (kc < 7) {
            STAGE_CHUNK((kc + 1) & 1, kc + 1);
            CP_WAIT(1);
        } else {
            CP_WAIT(0);
        }
        __syncthreads();
        CHUNK_COMPUTE(kc & 1);
        __syncthreads();
    }

    // epilogue: relu(+bias)*rho, reduce cols, per-row sums, per-b atomics
#pragma unroll
    for (int mt = 0; mt < 2; mt++) {
        float s0 = 0.0f, s1 = 0.0f;
#pragma unroll
        for (int nt = 0; nt < 8; nt++) {
            int c = warp_n * 64 + nt * 8 + (lane & 3) * 2;
            float b0v = sb[c], b1v = sb[c + 1];
            float r0v = sr[c], r1v = sr[c + 1];
            s0 += fmaxf(acc[mt][nt][0] + b0v, 0.0f) * r0v;
            s0 += fmaxf(acc[mt][nt][1] + b1v, 0.0f) * r1v;
            s1 += fmaxf(acc[mt][nt][2] + b0v, 0.0f) * r0v;
            s1 += fmaxf(acc[mt][nt][3] + b1v, 0.0f) * r1v;
        }
        s0 += __shfl_xor_sync(0xffffffffu, s0, 1);
        s0 += __shfl_xor_sync(0xffffffffu, s0, 2);
        s1 += __shfl_xor_sync(0xffffffffu, s1, 1);
        s1 += __shfl_xor_sync(0xffffffffu, s1, 2);
        if ((lane & 3) == 0) {
            int row = warp_m * 32 + mt * 16 + (lane >> 2);
            atomicAdd(&s_arr[row], s0);
            atomicAdd(&s_arr[row + 8], s1);
        }
    }
    __syncthreads();

    {
        int bfirst = m0 / 5;
        int blast  = (m0 + 127) / 5;
        int ng = blast - bfirst + 1;
        if (t < ng) {
            int b = bfirst + t;
            float s = 0.0f;
#pragma unroll
            for (int r = 0; r < 5; r++) {
                int m = b * 5 + r;
                if (m >= m0 && m < m0 + 128) s += s_arr[m - m0];
            }
            atomicAdd(&out[br * B + b], s);
        }
    }
}

// ---------------------------------------------------------------------------
extern "C" void kernel_launch(void* const* d_in, const int* in_sizes, int n_in,
                              void* d_out, int out_size)
{
    const float* obs    = (const float*)d_in[0];
    const float* act    = (const float*)d_in[1];
    const float* ag     = (const float*)d_in[2];
    const float* g      = (const float*)d_in[3];
    const float* mp_w   = (const float*)d_in[4];
    const float* mp_b   = (const float*)d_in[5];
    const float* phi_w1 = (const float*)d_in[6];
    const float* phi_b1 = (const float*)d_in[7];
    const float* phi_w2 = (const float*)d_in[8];
    const float* phi_b2 = (const float*)d_in[9];
    const float* phi_w3 = (const float*)d_in[10];
    const float* phi_b3 = (const float*)d_in[11];
    const float* phi_w4 = (const float*)d_in[12];
    const float* phi_b4 = (const float*)d_in[13];
    const float* rho_w1 = (const float*)d_in[14];
    const float* rho_b1 = (const float*)d_in[15];
    const float* rho_w2 = (const float*)d_in[16];
    const float* rho_b2 = (const float*)d_in[17];
    float* out = (float*)d_out;

    const int B = in_sizes[1] / 4;  // act is (B,4)
    const int nrows = B * 5;

    const int S1 = (46 * 128 + 8 * 132) * 4;   // 27,776 B
    cudaFuncSetAttribute(k_edge, cudaFuncAttributeMaxDynamicSharedMemorySize, S1);
    cudaFuncSetAttribute(k_phi1_mma, cudaFuncAttributeMaxDynamicSharedMemorySize, PP_SMEM);
    cudaFuncSetAttribute(k_phi2_mma, cudaFuncAttributeMaxDynamicSharedMemorySize, PP_SMEM);

    k_wconv<<<(512 * 160 + 512 * 256 + 255) / 256, 256>>>(phi_w1, phi_w3, phi_w2, phi_w4);
    k_edge<<<B / 8, 256, S1>>>(obs, act, ag, g, mp_w, mp_b);
    k_prep<<<(nrows * 32 + 255) / 256, 256>>>(obs, act, nrows);
    k_phi1_mma<<<dim3(nrows / 128, 4), 256, PP_SMEM>>>(phi_b1, phi_b3);
    k_init<<<(B + 255) / 256, 256>>>(out, rho_b1, rho_b2, B);
    k_phi2_mma<<<dim3(nrows / 128, 2, 2), 256, PP_SMEM>>>(
        phi_b2, phi_b4, rho_w1, rho_w2, out, B);
}